// round 1
// baseline (speedup 1.0000x reference)
#include <cuda_runtime.h>
#include <math.h>

#define BB 2
#define LL 401
#define DD 128
#define NBI (BB*LL)   // 802

// Scratch (static __device__ arrays per allocation rules)
__device__ float g_tmp[(size_t)NBI * DD * DD];   // 52.6 MB: tmp[b,i,k,e]
__device__ float g_C[(size_t)BB * LL * LL];      // contact before symmetrization

// ---------------------------------------------------------------------------
// Kernel 1: tmp[bi][k][e] = sum_d x[bi][d] * W_bil[k][d][e]
// Viewed as GEMM: C[802 x 16384] = X[802 x 128] @ B[128 x 16384],
// n-tile of 128 == one k slice (W_bil[k] is a contiguous 128x128 block).
// ---------------------------------------------------------------------------
__global__ __launch_bounds__(256) void k1_tmp(const float* __restrict__ x,
                                              const float* __restrict__ Wb)
{
    extern __shared__ float sm[];
    float* As = sm;              // [64][128]
    float* Bs = sm + 64 * 128;   // [128][128] = W_bil[k][d][e]

    const int k   = blockIdx.x;        // 0..127
    const int m0  = blockIdx.y * 64;   // bi tile
    const int tid = threadIdx.x;
    const int tx  = tid & 31, ty = tid >> 5;

    #pragma unroll
    for (int s = 0; s < 32; ++s) {
        int idx = tid + (s << 8);
        int row = idx >> 7, d = idx & 127;
        int bi  = m0 + row;
        As[idx] = (bi < NBI) ? x[bi * DD + d] : 0.0f;
    }
    const float* Wk = Wb + (size_t)k * DD * DD;
    #pragma unroll
    for (int s = 0; s < 64; ++s) {
        int idx = tid + (s << 8);
        Bs[idx] = Wk[idx];
    }
    __syncthreads();

    float acc[8][4];
    #pragma unroll
    for (int r = 0; r < 8; ++r)
        #pragma unroll
        for (int c = 0; c < 4; ++c) acc[r][c] = 0.0f;

    #pragma unroll 2
    for (int d = 0; d < DD; d += 4) {
        float av[8][4];
        #pragma unroll
        for (int r = 0; r < 8; ++r) {
            float4 t = *(const float4*)&As[(ty * 8 + r) * 128 + d];
            av[r][0] = t.x; av[r][1] = t.y; av[r][2] = t.z; av[r][3] = t.w;
        }
        #pragma unroll
        for (int q = 0; q < 4; ++q) {
            float bv[4];
            #pragma unroll
            for (int c = 0; c < 4; ++c) bv[c] = Bs[(d + q) * 128 + c * 32 + tx];
            #pragma unroll
            for (int r = 0; r < 8; ++r)
                #pragma unroll
                for (int c = 0; c < 4; ++c)
                    acc[r][c] = fmaf(av[r][q], bv[c], acc[r][c]);
        }
    }

    #pragma unroll
    for (int r = 0; r < 8; ++r) {
        int bi = m0 + ty * 8 + r;
        if (bi < NBI) {
            float* dst = &g_tmp[(size_t)bi * DD * DD + k * DD + tx];
            #pragma unroll
            for (int c = 0; c < 4; ++c) dst[c * 32] = acc[r][c];
        }
    }
}

// ---------------------------------------------------------------------------
// Kernel 2: per (b,i) CTA, fused:
//   pair = X_b @ tmp_i^T + b_bil      (phase A, registers)
//   LayerNorm over k (warp shuffles)  -> h written to smem (reuses Xs)
//   o = h @ W1^T + b1; gelu; dot(w2)  (phase B + epilogue)
//   -> g_C[b,i,j]
// ---------------------------------------------------------------------------
__global__ __launch_bounds__(256, 1) void k2_fused(
    const float* __restrict__ x,   const float* __restrict__ b_bil,
    const float* __restrict__ ln_g, const float* __restrict__ ln_b,
    const float* __restrict__ W1,  const float* __restrict__ b1,
    const float* __restrict__ w2,  const float* __restrict__ b2)
{
    extern __shared__ float sm[];
    float* Ts  = sm;                 // [128][132]  tmp_i  (padded row 132)
    float* W1s = Ts + 128 * 132;     // [128][132]  W1[e][d]
    float* Xs  = W1s + 128 * 132;    // [64][132]   x_j tile, reused as H
    float* cv  = Xs + 64 * 132;      // 5*128 constants
    float* bbs = cv;        float* lgs = cv + 128; float* lbs = cv + 256;
    float* b1s = cv + 384;  float* w2s = cv + 512;

    const int bi  = blockIdx.x;
    const int b   = bi / LL, i = bi % LL;
    const int tid = threadIdx.x, tx = tid & 31, ty = tid >> 5;

    const float* tptr = g_tmp + (size_t)bi * DD * DD;
    #pragma unroll
    for (int s = 0; s < 64; ++s) {
        int idx = tid + (s << 8);
        int k = idx >> 7, e = idx & 127;
        Ts[k * 132 + e]  = tptr[idx];
        W1s[k * 132 + e] = W1[idx];
    }
    if (tid < 128) {
        bbs[tid] = b_bil[tid]; lgs[tid] = ln_g[tid]; lbs[tid] = ln_b[tid];
        b1s[tid] = b1[tid];    w2s[tid] = w2[tid];
    }
    __syncthreads();

    float bbv[4], lgv[4], lbv[4], b1v[4], w2v[4];
    #pragma unroll
    for (int c = 0; c < 4; ++c) {
        int kk = c * 32 + tx;
        bbv[c] = bbs[kk]; lgv[c] = lgs[kk]; lbv[c] = lbs[kk];
        b1v[c] = b1s[kk]; w2v[c] = w2s[kk];
    }
    const float b2v = b2[0];
    const float* xb = x + (size_t)b * LL * DD;
    float* Crow = g_C + ((size_t)b * LL + i) * LL;

    for (int j0 = 0; j0 < LL; j0 += 64) {
        #pragma unroll
        for (int s = 0; s < 32; ++s) {
            int idx = tid + (s << 8);
            int jj = idx >> 7, e = idx & 127;
            int j = j0 + jj;
            Xs[jj * 132 + e] = (j < LL) ? xb[(size_t)j * DD + e] : 0.0f;
        }
        __syncthreads();

        // ---- Phase A: pair[j,k] = sum_e Xs[j][e] * Ts[k][e] ----
        float acc[8][4];
        #pragma unroll
        for (int r = 0; r < 8; ++r)
            #pragma unroll
            for (int c = 0; c < 4; ++c) acc[r][c] = 0.0f;

        #pragma unroll 2
        for (int e = 0; e < DD; e += 4) {
            float xv[8][4];
            #pragma unroll
            for (int r = 0; r < 8; ++r) {
                float4 t = *(const float4*)&Xs[(ty * 8 + r) * 132 + e];
                xv[r][0] = t.x; xv[r][1] = t.y; xv[r][2] = t.z; xv[r][3] = t.w;
            }
            float tv[4][4];
            #pragma unroll
            for (int c = 0; c < 4; ++c) {
                float4 t = *(const float4*)&Ts[(c * 32 + tx) * 132 + e];
                tv[c][0] = t.x; tv[c][1] = t.y; tv[c][2] = t.z; tv[c][3] = t.w;
            }
            #pragma unroll
            for (int r = 0; r < 8; ++r)
                #pragma unroll
                for (int c = 0; c < 4; ++c)
                    #pragma unroll
                    for (int q = 0; q < 4; ++q)
                        acc[r][c] = fmaf(xv[r][q], tv[c][q], acc[r][c]);
        }

        // ---- LayerNorm stats (per j row, across warp lanes) + write H ----
        #pragma unroll
        for (int r = 0; r < 8; ++r) {
            float p[4]; float s1 = 0.0f, s2 = 0.0f;
            #pragma unroll
            for (int c = 0; c < 4; ++c) {
                p[c] = acc[r][c] + bbv[c];
                s1 += p[c]; s2 += p[c] * p[c];
            }
            #pragma unroll
            for (int off = 16; off > 0; off >>= 1) {
                s1 += __shfl_xor_sync(0xffffffffu, s1, off);
                s2 += __shfl_xor_sync(0xffffffffu, s2, off);
            }
            float mu  = s1 * (1.0f / 128.0f);
            float var = s2 * (1.0f / 128.0f) - mu * mu;
            float inv = rsqrtf(var + 1e-5f);
            #pragma unroll
            for (int c = 0; c < 4; ++c)
                Xs[(ty * 8 + r) * 132 + c * 32 + tx] =
                    (p[c] - mu) * inv * lgv[c] + lbv[c];
        }
        __syncwarp();   // warp ty only touches its own 8 rows of Xs/H

        // ---- Phase B: o[j,e] = sum_d H[j][d] * W1[e][d] ----
        float acc2[8][4];
        #pragma unroll
        for (int r = 0; r < 8; ++r)
            #pragma unroll
            for (int c = 0; c < 4; ++c) acc2[r][c] = 0.0f;

        #pragma unroll 2
        for (int d = 0; d < DD; d += 4) {
            float hv[8][4];
            #pragma unroll
            for (int r = 0; r < 8; ++r) {
                float4 t = *(const float4*)&Xs[(ty * 8 + r) * 132 + d];
                hv[r][0] = t.x; hv[r][1] = t.y; hv[r][2] = t.z; hv[r][3] = t.w;
            }
            float wv[4][4];
            #pragma unroll
            for (int c = 0; c < 4; ++c) {
                float4 t = *(const float4*)&W1s[(c * 32 + tx) * 132 + d];
                wv[c][0] = t.x; wv[c][1] = t.y; wv[c][2] = t.z; wv[c][3] = t.w;
            }
            #pragma unroll
            for (int r = 0; r < 8; ++r)
                #pragma unroll
                for (int c = 0; c < 4; ++c)
                    #pragma unroll
                    for (int q = 0; q < 4; ++q)
                        acc2[r][c] = fmaf(hv[r][q], wv[c][q], acc2[r][c]);
        }

        // ---- Epilogue: bias, exact GELU, dot with w2, + b2 ----
        #pragma unroll
        for (int r = 0; r < 8; ++r) {
            float csum = 0.0f;
            #pragma unroll
            for (int c = 0; c < 4; ++c) {
                float v = acc2[r][c] + b1v[c];
                float g = 0.5f * v * (1.0f + erff(v * 0.70710678118654752f));
                csum += g * w2v[c];
            }
            #pragma unroll
            for (int off = 16; off > 0; off >>= 1)
                csum += __shfl_xor_sync(0xffffffffu, csum, off);
            int j = j0 + ty * 8 + r;
            if (tx == 0 && j < LL) Crow[j] = csum + b2v;
        }
        __syncthreads();
    }
}

// ---------------------------------------------------------------------------
// Kernel 3: out[b,i,j] = 0.5 * (C[b,i,j] + C[b,j,i])
// ---------------------------------------------------------------------------
__global__ void k3_sym(float* __restrict__ out)
{
    int idx = blockIdx.x * 256 + threadIdx.x;
    if (idx >= BB * LL * LL) return;
    int b  = idx / (LL * LL);
    int rm = idx - b * LL * LL;
    int i  = rm / LL, j = rm % LL;
    out[idx] = 0.5f * (g_C[idx] + g_C[((size_t)b * LL + j) * LL + i]);
}

// ---------------------------------------------------------------------------
extern "C" void kernel_launch(void* const* d_in, const int* in_sizes, int n_in,
                              void* d_out, int out_size)
{
    (void)in_sizes; (void)n_in; (void)out_size;
    const float* x     = (const float*)d_in[0];
    const float* W_bil = (const float*)d_in[1];
    const float* b_bil = (const float*)d_in[2];
    const float* ln_g  = (const float*)d_in[3];
    const float* ln_b  = (const float*)d_in[4];
    const float* W1    = (const float*)d_in[5];
    const float* b1    = (const float*)d_in[6];
    const float* w2    = (const float*)d_in[7];
    const float* b2    = (const float*)d_in[8];
    float* out = (float*)d_out;

    const int smem1 = (64 * 128 + 128 * 128) * 4;                       // 96 KB
    const int smem2 = (128 * 132 + 128 * 132 + 64 * 132 + 5 * 128) * 4; // ~168 KB
    cudaFuncSetAttribute(k1_tmp,  cudaFuncAttributeMaxDynamicSharedMemorySize, smem1);
    cudaFuncSetAttribute(k2_fused, cudaFuncAttributeMaxDynamicSharedMemorySize, smem2);

    dim3 g1(128, (NBI + 63) / 64);   // 128 x 13
    k1_tmp<<<g1, 256, smem1>>>(x, W_bil);
    k2_fused<<<NBI, 256, smem2>>>(x, b_bil, ln_g, ln_b, W1, b1, w2, b2);

    int tot = BB * LL * LL;
    k3_sym<<<(tot + 255) / 256, 256>>>(out);
}

// round 2
// speedup vs baseline: 2.0213x; 2.0213x over previous
#include <cuda_runtime.h>
#include <math.h>
#include <stdint.h>

#define BB 2
#define LL 401
#define DD 128
#define NBI (BB*LL)   // 802

// Scratch (static __device__ arrays per allocation rules)
__device__ float g_tmp[(size_t)NBI * DD * DD];   // 52.6 MB: tmp[b,i,k,e]
__device__ float g_C[(size_t)BB * LL * LL];      // contact before symmetrization

// ---------------------------------------------------------------------------
// Helpers
// ---------------------------------------------------------------------------
__device__ __forceinline__ float tf32r(float f) {
    uint32_t u;
    asm("cvt.rna.tf32.f32 %0, %1;" : "=r"(u) : "f"(f));
    return __uint_as_float(u);
}
__device__ __forceinline__ uint32_t fu(float f) { return __float_as_uint(f); }

__device__ __forceinline__ void mma_tf32(float c[4],
                                         uint32_t a0, uint32_t a1, uint32_t a2, uint32_t a3,
                                         uint32_t b0, uint32_t b1)
{
    asm volatile(
        "mma.sync.aligned.m16n8k8.row.col.f32.tf32.tf32.f32 "
        "{%0,%1,%2,%3}, {%4,%5,%6,%7}, {%8,%9}, {%0,%1,%2,%3};"
        : "+f"(c[0]), "+f"(c[1]), "+f"(c[2]), "+f"(c[3])
        : "r"(a0), "r"(a1), "r"(a2), "r"(a3), "r"(b0), "r"(b1));
}

// ---------------------------------------------------------------------------
// Kernel 1: tmp[bi][k][e] = sum_d x[bi][d] * W_bil[k][d][e]   (fp32 FFMA)
// ---------------------------------------------------------------------------
__global__ __launch_bounds__(256) void k1_tmp(const float* __restrict__ x,
                                              const float* __restrict__ Wb)
{
    extern __shared__ float sm[];
    float* As = sm;              // [64][128]
    float* Bs = sm + 64 * 128;   // [128][128] = W_bil[k][d][e]

    const int k   = blockIdx.x;
    const int m0  = blockIdx.y * 64;
    const int tid = threadIdx.x;
    const int tx  = tid & 31, ty = tid >> 5;

    #pragma unroll
    for (int s = 0; s < 32; ++s) {
        int idx = tid + (s << 8);
        int row = idx >> 7, d = idx & 127;
        int bi  = m0 + row;
        As[idx] = (bi < NBI) ? x[bi * DD + d] : 0.0f;
    }
    const float* Wk = Wb + (size_t)k * DD * DD;
    #pragma unroll
    for (int s = 0; s < 64; ++s) {
        int idx = tid + (s << 8);
        Bs[idx] = Wk[idx];
    }
    __syncthreads();

    float acc[8][4];
    #pragma unroll
    for (int r = 0; r < 8; ++r)
        #pragma unroll
        for (int c = 0; c < 4; ++c) acc[r][c] = 0.0f;

    #pragma unroll 2
    for (int d = 0; d < DD; d += 4) {
        float av[8][4];
        #pragma unroll
        for (int r = 0; r < 8; ++r) {
            float4 t = *(const float4*)&As[(ty * 8 + r) * 128 + d];
            av[r][0] = t.x; av[r][1] = t.y; av[r][2] = t.z; av[r][3] = t.w;
        }
        #pragma unroll
        for (int q = 0; q < 4; ++q) {
            float bv[4];
            #pragma unroll
            for (int c = 0; c < 4; ++c) bv[c] = Bs[(d + q) * 128 + c * 32 + tx];
            #pragma unroll
            for (int r = 0; r < 8; ++r)
                #pragma unroll
                for (int c = 0; c < 4; ++c)
                    acc[r][c] = fmaf(av[r][q], bv[c], acc[r][c]);
        }
    }

    #pragma unroll
    for (int r = 0; r < 8; ++r) {
        int bi = m0 + ty * 8 + r;
        if (bi < NBI) {
            float* dst = &g_tmp[(size_t)bi * DD * DD + k * DD + tx];
            #pragma unroll
            for (int c = 0; c < 4; ++c) dst[c * 32] = acc[r][c];
        }
    }
}

// ---------------------------------------------------------------------------
// Kernel 2: per (b,i) CTA, fused, tensor-core (tf32 mma.sync):
//   pair = X_b @ tmp_i^T + b_bil      (mma, 64j x 128k per tile)
//   LayerNorm over k                  -> H (tf32-rounded) into Xs smem
//   o = H @ W1^T + b1; gelu; dot(w2)  (mma + epilogue)
// Warp layout: 8 warps = (wj 0..3) x (wk 0..1); warp tile = 16 j x 64 n.
// ---------------------------------------------------------------------------
__global__ __launch_bounds__(256, 1) void k2_fused(
    const float* __restrict__ x,    const float* __restrict__ b_bil,
    const float* __restrict__ ln_g, const float* __restrict__ ln_b,
    const float* __restrict__ W1,   const float* __restrict__ b1,
    const float* __restrict__ w2,   const float* __restrict__ b2)
{
    extern __shared__ float sm[];
    float* Ts  = sm;                 // [128][132]  tmp_i (tf32-rounded)
    float* W1s = Ts + 128 * 132;     // [128][132]  W1[e][d] (tf32-rounded)
    float* Xs  = W1s + 128 * 132;    // [64][132]   x_j tile (tf32), reused as H
    float* cv  = Xs + 64 * 132;
    float* bbs = cv;        float* lgs = cv + 128; float* lbs = cv + 256;
    float* b1s = cv + 384;  float* w2s = cv + 512;
    float* red = cv + 640;           // [64][2][2] reduction buffer (256 floats)

    const int bi  = blockIdx.x;
    const int b   = bi / LL;
    const int tid = threadIdx.x;
    const int tx  = tid & 31;
    const int wid = tid >> 5;
    const int wj  = wid & 3;         // j-slice 16 rows
    const int wk  = wid >> 2;        // n-half 64 cols
    const int g   = tx >> 2;         // row-in-frag group (0..7)
    const int c   = tx & 3;          // col-in-frag (0..3)

    // Load tmp_i and W1 (tf32-rounded), vectorized
    const float* tptr = g_tmp + (size_t)bi * DD * DD;
    #pragma unroll
    for (int s = 0; s < 16; ++s) {
        int v = tid + (s << 8);          // float4 index, 4096 total
        int row = v >> 5, col4 = (v & 31) << 2;
        float4 t = *(const float4*)&tptr[row * DD + col4];
        float* d = &Ts[row * 132 + col4];
        d[0] = tf32r(t.x); d[1] = tf32r(t.y); d[2] = tf32r(t.z); d[3] = tf32r(t.w);
        float4 w = *(const float4*)&W1[row * DD + col4];
        float* e = &W1s[row * 132 + col4];
        e[0] = tf32r(w.x); e[1] = tf32r(w.y); e[2] = tf32r(w.z); e[3] = tf32r(w.w);
    }
    if (tid < 128) {
        bbs[tid] = b_bil[tid]; lgs[tid] = ln_g[tid]; lbs[tid] = ln_b[tid];
        b1s[tid] = b1[tid];    w2s[tid] = w2[tid];
    }
    const float b2v = b2[0];
    const float* xb = x + (size_t)b * LL * DD;
    float* Crow = g_C + (size_t)bi * LL;

    const float* Aw = Xs  + (wj * 16) * 132;   // A rows for this warp
    const float* Bt = Ts  + (wk * 64) * 132;   // B (phase A) rows
    const float* Bw = W1s + (wk * 64) * 132;   // B (phase B) rows
    const int rowA = wj * 16 + g;              // tile-row of acc[..][0..1]
    const int rowB = rowA + 8;                 // tile-row of acc[..][2..3]

    __syncthreads();

    for (int j0 = 0; j0 < 448; j0 += 64) {
        // ---- Load x_j tile (tf32-rounded, zero-padded) ----
        #pragma unroll
        for (int s = 0; s < 8; ++s) {
            int v = tid + (s << 8);          // float4 index, 2048 total
            int row = v >> 5, col4 = (v & 31) << 2;
            int j = j0 + row;
            float* d = &Xs[row * 132 + col4];
            if (j < LL) {
                float4 t = *(const float4*)&xb[(size_t)j * DD + col4];
                d[0] = tf32r(t.x); d[1] = tf32r(t.y); d[2] = tf32r(t.z); d[3] = tf32r(t.w);
            } else {
                d[0] = 0.0f; d[1] = 0.0f; d[2] = 0.0f; d[3] = 0.0f;
            }
        }
        __syncthreads();

        // ---- Phase A: pair[j, k] = X @ Ts^T ----
        float acc[8][4];
        #pragma unroll
        for (int nt = 0; nt < 8; ++nt)
            #pragma unroll
            for (int u = 0; u < 4; ++u) acc[nt][u] = 0.0f;

        #pragma unroll
        for (int kc = 0; kc < 16; ++kc) {
            int e0 = kc * 8;
            uint32_t a0 = fu(Aw[g * 132 + e0 + c]);
            uint32_t a1 = fu(Aw[(g + 8) * 132 + e0 + c]);
            uint32_t a2 = fu(Aw[g * 132 + e0 + c + 4]);
            uint32_t a3 = fu(Aw[(g + 8) * 132 + e0 + c + 4]);
            #pragma unroll
            for (int nt = 0; nt < 8; ++nt) {
                uint32_t b0 = fu(Bt[(nt * 8 + g) * 132 + e0 + c]);
                uint32_t b1r = fu(Bt[(nt * 8 + g) * 132 + e0 + c + 4]);
                mma_tf32(acc[nt], a0, a1, a2, a3, b0, b1r);
            }
        }

        // ---- LayerNorm stats ----
        float s1a = 0.f, s2a = 0.f, s1b = 0.f, s2b = 0.f;
        #pragma unroll
        for (int nt = 0; nt < 8; ++nt) {
            int col = wk * 64 + nt * 8 + 2 * c;
            float bb0 = bbs[col], bb1 = bbs[col + 1];
            acc[nt][0] += bb0; acc[nt][1] += bb1;
            acc[nt][2] += bb0; acc[nt][3] += bb1;
            s1a += acc[nt][0] + acc[nt][1];
            s2a += acc[nt][0] * acc[nt][0] + acc[nt][1] * acc[nt][1];
            s1b += acc[nt][2] + acc[nt][3];
            s2b += acc[nt][2] * acc[nt][2] + acc[nt][3] * acc[nt][3];
        }
        #pragma unroll
        for (int off = 1; off <= 2; off <<= 1) {
            s1a += __shfl_xor_sync(0xffffffffu, s1a, off);
            s2a += __shfl_xor_sync(0xffffffffu, s2a, off);
            s1b += __shfl_xor_sync(0xffffffffu, s1b, off);
            s2b += __shfl_xor_sync(0xffffffffu, s2b, off);
        }
        if (c == 0) {
            red[(rowA * 2 + wk) * 2 + 0] = s1a;
            red[(rowA * 2 + wk) * 2 + 1] = s2a;
            red[(rowB * 2 + wk) * 2 + 0] = s1b;
            red[(rowB * 2 + wk) * 2 + 1] = s2b;
        }
        __syncthreads();

        float S1a = red[(rowA * 2 + 0) * 2 + 0] + red[(rowA * 2 + 1) * 2 + 0];
        float S2a = red[(rowA * 2 + 0) * 2 + 1] + red[(rowA * 2 + 1) * 2 + 1];
        float S1b = red[(rowB * 2 + 0) * 2 + 0] + red[(rowB * 2 + 1) * 2 + 0];
        float S2b = red[(rowB * 2 + 0) * 2 + 1] + red[(rowB * 2 + 1) * 2 + 1];
        float mua = S1a * (1.0f / 128.0f);
        float rsa = rsqrtf(S2a * (1.0f / 128.0f) - mua * mua + 1e-5f);
        float mub = S1b * (1.0f / 128.0f);
        float rsb = rsqrtf(S2b * (1.0f / 128.0f) - mub * mub + 1e-5f);

        // ---- Write H (tf32-rounded) into Xs ----
        #pragma unroll
        for (int nt = 0; nt < 8; ++nt) {
            int col = wk * 64 + nt * 8 + 2 * c;
            float lg0 = lgs[col], lg1 = lgs[col + 1];
            float lb0 = lbs[col], lb1 = lbs[col + 1];
            Xs[rowA * 132 + col]     = tf32r((acc[nt][0] - mua) * rsa * lg0 + lb0);
            Xs[rowA * 132 + col + 1] = tf32r((acc[nt][1] - mua) * rsa * lg1 + lb1);
            Xs[rowB * 132 + col]     = tf32r((acc[nt][2] - mub) * rsb * lg0 + lb0);
            Xs[rowB * 132 + col + 1] = tf32r((acc[nt][3] - mub) * rsb * lg1 + lb1);
        }
        __syncthreads();

        // ---- Phase B: o[j, e] = H @ W1^T ----
        #pragma unroll
        for (int nt = 0; nt < 8; ++nt)
            #pragma unroll
            for (int u = 0; u < 4; ++u) acc[nt][u] = 0.0f;

        #pragma unroll
        for (int kc = 0; kc < 16; ++kc) {
            int e0 = kc * 8;
            uint32_t a0 = fu(Aw[g * 132 + e0 + c]);
            uint32_t a1 = fu(Aw[(g + 8) * 132 + e0 + c]);
            uint32_t a2 = fu(Aw[g * 132 + e0 + c + 4]);
            uint32_t a3 = fu(Aw[(g + 8) * 132 + e0 + c + 4]);
            #pragma unroll
            for (int nt = 0; nt < 8; ++nt) {
                uint32_t b0 = fu(Bw[(nt * 8 + g) * 132 + e0 + c]);
                uint32_t b1r = fu(Bw[(nt * 8 + g) * 132 + e0 + c + 4]);
                mma_tf32(acc[nt], a0, a1, a2, a3, b0, b1r);
            }
        }

        // ---- Epilogue: bias, exact GELU, dot w2 ----
        float ta = 0.f, tb = 0.f;
        #pragma unroll
        for (int nt = 0; nt < 8; ++nt) {
            int col = wk * 64 + nt * 8 + 2 * c;
            float c0 = b1s[col], c1 = b1s[col + 1];
            float w0 = w2s[col], w1 = w2s[col + 1];
            float v0 = acc[nt][0] + c0, v1 = acc[nt][1] + c1;
            float v2 = acc[nt][2] + c0, v3 = acc[nt][3] + c1;
            ta += 0.5f * v0 * (1.0f + erff(v0 * 0.70710678118654752f)) * w0;
            ta += 0.5f * v1 * (1.0f + erff(v1 * 0.70710678118654752f)) * w1;
            tb += 0.5f * v2 * (1.0f + erff(v2 * 0.70710678118654752f)) * w0;
            tb += 0.5f * v3 * (1.0f + erff(v3 * 0.70710678118654752f)) * w1;
        }
        #pragma unroll
        for (int off = 1; off <= 2; off <<= 1) {
            ta += __shfl_xor_sync(0xffffffffu, ta, off);
            tb += __shfl_xor_sync(0xffffffffu, tb, off);
        }
        if (c == 0) {
            red[rowA * 2 + wk] = ta;
            red[rowB * 2 + wk] = tb;
        }
        __syncthreads();

        if (tid < 64) {
            int j = j0 + tid;
            if (j < LL) Crow[j] = red[tid * 2] + red[tid * 2 + 1] + b2v;
        }
        __syncthreads();
    }
}

// ---------------------------------------------------------------------------
// Kernel 3: out[b,i,j] = 0.5 * (C[b,i,j] + C[b,j,i])
// ---------------------------------------------------------------------------
__global__ void k3_sym(float* __restrict__ out)
{
    int idx = blockIdx.x * 256 + threadIdx.x;
    if (idx >= BB * LL * LL) return;
    int b  = idx / (LL * LL);
    int rm = idx - b * LL * LL;
    int i  = rm / LL, j = rm % LL;
    out[idx] = 0.5f * (g_C[idx] + g_C[((size_t)b * LL + j) * LL + i]);
}

// ---------------------------------------------------------------------------
extern "C" void kernel_launch(void* const* d_in, const int* in_sizes, int n_in,
                              void* d_out, int out_size)
{
    (void)in_sizes; (void)n_in; (void)out_size;
    const float* x     = (const float*)d_in[0];
    const float* W_bil = (const float*)d_in[1];
    const float* b_bil = (const float*)d_in[2];
    const float* ln_g  = (const float*)d_in[3];
    const float* ln_b  = (const float*)d_in[4];
    const float* W1    = (const float*)d_in[5];
    const float* b1    = (const float*)d_in[6];
    const float* w2    = (const float*)d_in[7];
    const float* b2    = (const float*)d_in[8];
    float* out = (float*)d_out;

    const int smem1 = (64 * 128 + 128 * 128) * 4;                              // 96 KB
    const int smem2 = (128 * 132 + 128 * 132 + 64 * 132 + 640 + 256) * 4;      // ~173 KB
    cudaFuncSetAttribute(k1_tmp,   cudaFuncAttributeMaxDynamicSharedMemorySize, smem1);
    cudaFuncSetAttribute(k2_fused, cudaFuncAttributeMaxDynamicSharedMemorySize, smem2);

    dim3 g1(128, (NBI + 63) / 64);
    k1_tmp<<<g1, 256, smem1>>>(x, W_bil);
    k2_fused<<<NBI, 256, smem2>>>(x, b_bil, ln_g, ln_b, W1, b1, w2, b2);

    int tot = BB * LL * LL;
    k3_sym<<<(tot + 255) / 256, 256>>>(out);
}

// round 3
// speedup vs baseline: 2.3416x; 1.1585x over previous
#include <cuda_runtime.h>
#include <math.h>
#include <stdint.h>

#define BB 2
#define LL 401
#define DD 128
#define NBI (BB*LL)   // 802

// Scratch (static __device__ arrays per allocation rules)
__device__ float g_tmp[(size_t)NBI * DD * DD];   // 52.6 MB: tmp[b,i,k,e]
__device__ float g_C[(size_t)BB * LL * LL];      // contact before symmetrization

// ---------------------------------------------------------------------------
// Helpers
// ---------------------------------------------------------------------------
__device__ __forceinline__ float tf32r(float f) {
    uint32_t u;
    asm("cvt.rna.tf32.f32 %0, %1;" : "=r"(u) : "f"(f));
    return __uint_as_float(u);
}
__device__ __forceinline__ uint32_t fu(float f) { return __float_as_uint(f); }

__device__ __forceinline__ void mma_tf32(float c[4],
                                         uint32_t a0, uint32_t a1, uint32_t a2, uint32_t a3,
                                         uint32_t b0, uint32_t b1)
{
    asm volatile(
        "mma.sync.aligned.m16n8k8.row.col.f32.tf32.tf32.f32 "
        "{%0,%1,%2,%3}, {%4,%5,%6,%7}, {%8,%9}, {%0,%1,%2,%3};"
        : "+f"(c[0]), "+f"(c[1]), "+f"(c[2]), "+f"(c[3])
        : "r"(a0), "r"(a1), "r"(a2), "r"(a3), "r"(b0), "r"(b1));
}

// ---------------------------------------------------------------------------
// Kernel 1 (tf32 mma): tmp[bi][k][e] = sum_d x[bi][d] * W_bil[k][d][e]
// Per block: one k-slice, 128 bi rows x 128 e cols. Warps 4(wj) x 2(wk),
// warp tile 32m x 64n. A = x rows (row-major, pad 132, conflict-free).
// B = Wk stored [d][e] pad 132; frag B[n=e][k=d] reads <=2-way conflicted.
// ---------------------------------------------------------------------------
__global__ __launch_bounds__(256, 1) void k1_tmp(const float* __restrict__ x,
                                                 const float* __restrict__ Wb)
{
    extern __shared__ float sm[];
    float* Xs = sm;              // [128][132] x rows (tf32)
    float* Ws = sm + 128 * 132;  // [128][132] Wk[d][e] (tf32)

    const int k   = blockIdx.x;
    const int bi0 = blockIdx.y * 128;
    const int tid = threadIdx.x, tx = tid & 31, wid = tid >> 5;
    const int wj  = wid & 3, wk = wid >> 2;
    const int g   = tx >> 2, c = tx & 3;

    const float* Wk = Wb + (size_t)k * DD * DD;
    #pragma unroll
    for (int s = 0; s < 16; ++s) {
        int v = tid + (s << 8);              // float4 index, 4096 total
        int row = v >> 5, col4 = (v & 31) << 2;
        float* d = &Xs[row * 132 + col4];
        int bi = bi0 + row;
        if (bi < NBI) {
            float4 t = *(const float4*)&x[(size_t)bi * DD + col4];
            d[0] = tf32r(t.x); d[1] = tf32r(t.y); d[2] = tf32r(t.z); d[3] = tf32r(t.w);
        } else {
            d[0] = 0.f; d[1] = 0.f; d[2] = 0.f; d[3] = 0.f;
        }
        float4 w = *(const float4*)&Wk[row * DD + col4];
        float* e = &Ws[row * 132 + col4];
        e[0] = tf32r(w.x); e[1] = tf32r(w.y); e[2] = tf32r(w.z); e[3] = tf32r(w.w);
    }
    __syncthreads();

    float acc[2][8][4];
    #pragma unroll
    for (int mf = 0; mf < 2; ++mf)
        #pragma unroll
        for (int nt = 0; nt < 8; ++nt)
            #pragma unroll
            for (int u = 0; u < 4; ++u) acc[mf][nt][u] = 0.0f;

    const int arow = wj * 32, bcol = wk * 64;

    #pragma unroll
    for (int d0 = 0; d0 < DD; d0 += 8) {
        uint32_t a[2][4];
        #pragma unroll
        for (int mf = 0; mf < 2; ++mf) {
            const float* Ar = &Xs[(arow + mf * 16 + g) * 132 + d0];
            a[mf][0] = fu(Ar[c]);
            a[mf][1] = fu(Ar[8 * 132 + c]);
            a[mf][2] = fu(Ar[c + 4]);
            a[mf][3] = fu(Ar[8 * 132 + c + 4]);
        }
        #pragma unroll
        for (int nt = 0; nt < 8; ++nt) {
            uint32_t b0 = fu(Ws[(d0 + c) * 132 + bcol + nt * 8 + g]);
            uint32_t b1 = fu(Ws[(d0 + c + 4) * 132 + bcol + nt * 8 + g]);
            mma_tf32(acc[0][nt], a[0][0], a[0][1], a[0][2], a[0][3], b0, b1);
            mma_tf32(acc[1][nt], a[1][0], a[1][1], a[1][2], a[1][3], b0, b1);
        }
    }

    #pragma unroll
    for (int mf = 0; mf < 2; ++mf)
        #pragma unroll
        for (int nt = 0; nt < 8; ++nt) {
            int r0  = bi0 + arow + mf * 16 + g;
            int col = bcol + nt * 8 + 2 * c;
            if (r0 < NBI) {
                float2 v = {acc[mf][nt][0], acc[mf][nt][1]};
                *(float2*)&g_tmp[(size_t)r0 * (DD * DD) + k * DD + col] = v;
            }
            int r1 = r0 + 8;
            if (r1 < NBI) {
                float2 v = {acc[mf][nt][2], acc[mf][nt][3]};
                *(float2*)&g_tmp[(size_t)r1 * (DD * DD) + k * DD + col] = v;
            }
        }
}

// ---------------------------------------------------------------------------
// Kernel 2: per (b,i) CTA, fused tf32-mma pipeline, j-tile = 128 rows.
// Warps 4(wj) x 2(wk), warp tile 32m x 64n (2 m-frags reuse each B-frag).
//   pair = X_b @ tmp_i^T + b_bil -> LayerNorm -> H (tf32, in Xs)
//   o = H @ W1^T + b1 -> exact GELU -> dot(w2) -> g_C
// ---------------------------------------------------------------------------
__global__ __launch_bounds__(256, 1) void k2_fused(
    const float* __restrict__ x,    const float* __restrict__ b_bil,
    const float* __restrict__ ln_g, const float* __restrict__ ln_b,
    const float* __restrict__ W1,   const float* __restrict__ b1,
    const float* __restrict__ w2,   const float* __restrict__ b2)
{
    extern __shared__ float sm[];
    float* Ts  = sm;                 // [128][132] tmp_i (tf32)
    float* W1s = Ts + 128 * 132;     // [128][132] W1[e][d] (tf32)
    float* Xs  = W1s + 128 * 132;    // [128][132] x_j tile (tf32) / H
    float* cv  = Xs + 128 * 132;
    float* bbs = cv;        float* lgs = cv + 128; float* lbs = cv + 256;
    float* b1s = cv + 384;  float* w2s = cv + 512;
    float* red = cv + 640;           // [128][2][2]

    const int bi  = blockIdx.x;
    const int b   = bi / LL;
    const int tid = threadIdx.x, tx = tid & 31, wid = tid >> 5;
    const int wj  = wid & 3, wk = wid >> 2;
    const int g   = tx >> 2, c = tx & 3;
    const int arow = wj * 32, bcol = wk * 64;

    // Load tmp_i and W1 (tf32-rounded)
    const float* tptr = g_tmp + (size_t)bi * DD * DD;
    #pragma unroll
    for (int s = 0; s < 16; ++s) {
        int v = tid + (s << 8);
        int row = v >> 5, col4 = (v & 31) << 2;
        float4 t = *(const float4*)&tptr[row * DD + col4];
        float* d = &Ts[row * 132 + col4];
        d[0] = tf32r(t.x); d[1] = tf32r(t.y); d[2] = tf32r(t.z); d[3] = tf32r(t.w);
        float4 w = *(const float4*)&W1[row * DD + col4];
        float* e = &W1s[row * 132 + col4];
        e[0] = tf32r(w.x); e[1] = tf32r(w.y); e[2] = tf32r(w.z); e[3] = tf32r(w.w);
    }
    if (tid < 128) {
        bbs[tid] = b_bil[tid]; lgs[tid] = ln_g[tid]; lbs[tid] = ln_b[tid];
        b1s[tid] = b1[tid];    w2s[tid] = w2[tid];
    }
    const float b2v = b2[0];
    const float* xb = x + (size_t)b * LL * DD;
    float* Crow = g_C + (size_t)bi * LL;
    __syncthreads();

    for (int j0 = 0; j0 < 512; j0 += 128) {
        // ---- Load x_j tile (tf32, zero-pad) ----
        #pragma unroll
        for (int s = 0; s < 16; ++s) {
            int v = tid + (s << 8);
            int row = v >> 5, col4 = (v & 31) << 2;
            int j = j0 + row;
            float* d = &Xs[row * 132 + col4];
            if (j < LL) {
                float4 t = *(const float4*)&xb[(size_t)j * DD + col4];
                d[0] = tf32r(t.x); d[1] = tf32r(t.y); d[2] = tf32r(t.z); d[3] = tf32r(t.w);
            } else {
                d[0] = 0.f; d[1] = 0.f; d[2] = 0.f; d[3] = 0.f;
            }
        }
        __syncthreads();

        // ---- Phase A: pair = X @ Ts^T ----
        float acc[2][8][4];
        #pragma unroll
        for (int mf = 0; mf < 2; ++mf)
            #pragma unroll
            for (int nt = 0; nt < 8; ++nt)
                #pragma unroll
                for (int u = 0; u < 4; ++u) acc[mf][nt][u] = 0.0f;

        #pragma unroll
        for (int e0 = 0; e0 < DD; e0 += 8) {
            uint32_t a[2][4];
            #pragma unroll
            for (int mf = 0; mf < 2; ++mf) {
                const float* Ar = &Xs[(arow + mf * 16 + g) * 132 + e0];
                a[mf][0] = fu(Ar[c]);
                a[mf][1] = fu(Ar[8 * 132 + c]);
                a[mf][2] = fu(Ar[c + 4]);
                a[mf][3] = fu(Ar[8 * 132 + c + 4]);
            }
            #pragma unroll
            for (int nt = 0; nt < 8; ++nt) {
                const float* Br = &Ts[(bcol + nt * 8 + g) * 132 + e0];
                uint32_t b0 = fu(Br[c]);
                uint32_t b1r = fu(Br[c + 4]);
                mma_tf32(acc[0][nt], a[0][0], a[0][1], a[0][2], a[0][3], b0, b1r);
                mma_tf32(acc[1][nt], a[1][0], a[1][1], a[1][2], a[1][3], b0, b1r);
            }
        }

        // ---- LayerNorm stats (4 rows per thread: lr = mf*2 + half) ----
        float s1[4] = {0.f, 0.f, 0.f, 0.f}, s2[4] = {0.f, 0.f, 0.f, 0.f};
        #pragma unroll
        for (int mf = 0; mf < 2; ++mf)
            #pragma unroll
            for (int nt = 0; nt < 8; ++nt) {
                int col = bcol + nt * 8 + 2 * c;
                float bb0 = bbs[col], bb1 = bbs[col + 1];
                acc[mf][nt][0] += bb0; acc[mf][nt][1] += bb1;
                acc[mf][nt][2] += bb0; acc[mf][nt][3] += bb1;
                s1[mf * 2]     += acc[mf][nt][0] + acc[mf][nt][1];
                s2[mf * 2]     += acc[mf][nt][0] * acc[mf][nt][0] + acc[mf][nt][1] * acc[mf][nt][1];
                s1[mf * 2 + 1] += acc[mf][nt][2] + acc[mf][nt][3];
                s2[mf * 2 + 1] += acc[mf][nt][2] * acc[mf][nt][2] + acc[mf][nt][3] * acc[mf][nt][3];
            }
        #pragma unroll
        for (int off = 1; off <= 2; off <<= 1)
            #pragma unroll
            for (int lr = 0; lr < 4; ++lr) {
                s1[lr] += __shfl_xor_sync(0xffffffffu, s1[lr], off);
                s2[lr] += __shfl_xor_sync(0xffffffffu, s2[lr], off);
            }
        if (c == 0) {
            #pragma unroll
            for (int lr = 0; lr < 4; ++lr) {
                int row = arow + (lr >> 1) * 16 + (lr & 1) * 8 + g;
                red[row * 4 + wk * 2 + 0] = s1[lr];
                red[row * 4 + wk * 2 + 1] = s2[lr];
            }
        }
        __syncthreads();

        float mu[4], rs[4];
        #pragma unroll
        for (int lr = 0; lr < 4; ++lr) {
            int row = arow + (lr >> 1) * 16 + (lr & 1) * 8 + g;
            float S1 = red[row * 4 + 0] + red[row * 4 + 2];
            float S2 = red[row * 4 + 1] + red[row * 4 + 3];
            mu[lr] = S1 * (1.0f / 128.0f);
            rs[lr] = rsqrtf(S2 * (1.0f / 128.0f) - mu[lr] * mu[lr] + 1e-5f);
        }

        // ---- Write H (tf32) into Xs ----
        #pragma unroll
        for (int mf = 0; mf < 2; ++mf)
            #pragma unroll
            for (int nt = 0; nt < 8; ++nt) {
                int col = bcol + nt * 8 + 2 * c;
                float lg0 = lgs[col], lg1 = lgs[col + 1];
                float lb0 = lbs[col], lb1 = lbs[col + 1];
                int lr0 = mf * 2, lr1 = mf * 2 + 1;
                int r0 = arow + mf * 16 + g;
                float2 h0 = {tf32r((acc[mf][nt][0] - mu[lr0]) * rs[lr0] * lg0 + lb0),
                             tf32r((acc[mf][nt][1] - mu[lr0]) * rs[lr0] * lg1 + lb1)};
                *(float2*)&Xs[r0 * 132 + col] = h0;
                float2 h1 = {tf32r((acc[mf][nt][2] - mu[lr1]) * rs[lr1] * lg0 + lb0),
                             tf32r((acc[mf][nt][3] - mu[lr1]) * rs[lr1] * lg1 + lb1)};
                *(float2*)&Xs[(r0 + 8) * 132 + col] = h1;
            }
        __syncthreads();

        // ---- Phase B: o = H @ W1^T ----
        #pragma unroll
        for (int mf = 0; mf < 2; ++mf)
            #pragma unroll
            for (int nt = 0; nt < 8; ++nt)
                #pragma unroll
                for (int u = 0; u < 4; ++u) acc[mf][nt][u] = 0.0f;

        #pragma unroll
        for (int d0 = 0; d0 < DD; d0 += 8) {
            uint32_t a[2][4];
            #pragma unroll
            for (int mf = 0; mf < 2; ++mf) {
                const float* Ar = &Xs[(arow + mf * 16 + g) * 132 + d0];
                a[mf][0] = fu(Ar[c]);
                a[mf][1] = fu(Ar[8 * 132 + c]);
                a[mf][2] = fu(Ar[c + 4]);
                a[mf][3] = fu(Ar[8 * 132 + c + 4]);
            }
            #pragma unroll
            for (int nt = 0; nt < 8; ++nt) {
                const float* Br = &W1s[(bcol + nt * 8 + g) * 132 + d0];
                uint32_t b0 = fu(Br[c]);
                uint32_t b1r = fu(Br[c + 4]);
                mma_tf32(acc[0][nt], a[0][0], a[0][1], a[0][2], a[0][3], b0, b1r);
                mma_tf32(acc[1][nt], a[1][0], a[1][1], a[1][2], a[1][3], b0, b1r);
            }
        }

        // ---- Epilogue: bias, exact GELU, dot w2 ----
        float t[4] = {0.f, 0.f, 0.f, 0.f};
        #pragma unroll
        for (int mf = 0; mf < 2; ++mf)
            #pragma unroll
            for (int nt = 0; nt < 8; ++nt) {
                int col = bcol + nt * 8 + 2 * c;
                float c0 = b1s[col], c1 = b1s[col + 1];
                float w0 = w2s[col], w1 = w2s[col + 1];
                float v0 = acc[mf][nt][0] + c0, v1 = acc[mf][nt][1] + c1;
                float v2 = acc[mf][nt][2] + c0, v3 = acc[mf][nt][3] + c1;
                t[mf * 2]     += 0.5f * v0 * (1.0f + erff(v0 * 0.70710678118654752f)) * w0
                               + 0.5f * v1 * (1.0f + erff(v1 * 0.70710678118654752f)) * w1;
                t[mf * 2 + 1] += 0.5f * v2 * (1.0f + erff(v2 * 0.70710678118654752f)) * w0
                               + 0.5f * v3 * (1.0f + erff(v3 * 0.70710678118654752f)) * w1;
            }
        #pragma unroll
        for (int off = 1; off <= 2; off <<= 1)
            #pragma unroll
            for (int lr = 0; lr < 4; ++lr)
                t[lr] += __shfl_xor_sync(0xffffffffu, t[lr], off);
        if (c == 0) {
            #pragma unroll
            for (int lr = 0; lr < 4; ++lr) {
                int row = arow + (lr >> 1) * 16 + (lr & 1) * 8 + g;
                red[row * 2 + wk] = t[lr];
            }
        }
        __syncthreads();

        if (tid < 128) {
            int j = j0 + tid;
            if (j < LL) Crow[j] = red[tid * 2] + red[tid * 2 + 1] + b2v;
        }
        __syncthreads();
    }
}

// ---------------------------------------------------------------------------
// Kernel 3: out[b,i,j] = 0.5 * (C[b,i,j] + C[b,j,i])
// ---------------------------------------------------------------------------
__global__ void k3_sym(float* __restrict__ out)
{
    int idx = blockIdx.x * 256 + threadIdx.x;
    if (idx >= BB * LL * LL) return;
    int b  = idx / (LL * LL);
    int rm = idx - b * LL * LL;
    int i  = rm / LL, j = rm % LL;
    out[idx] = 0.5f * (g_C[idx] + g_C[((size_t)b * LL + j) * LL + i]);
}

// ---------------------------------------------------------------------------
extern "C" void kernel_launch(void* const* d_in, const int* in_sizes, int n_in,
                              void* d_out, int out_size)
{
    (void)in_sizes; (void)n_in; (void)out_size;
    const float* x     = (const float*)d_in[0];
    const float* W_bil = (const float*)d_in[1];
    const float* b_bil = (const float*)d_in[2];
    const float* ln_g  = (const float*)d_in[3];
    const float* ln_b  = (const float*)d_in[4];
    const float* W1    = (const float*)d_in[5];
    const float* b1    = (const float*)d_in[6];
    const float* w2    = (const float*)d_in[7];
    const float* b2    = (const float*)d_in[8];
    float* out = (float*)d_out;

    const int smem1 = 2 * 128 * 132 * 4;                          // 135 KB
    const int smem2 = (3 * 128 * 132 + 640 + 512) * 4;            // ~202.5 KB
    cudaFuncSetAttribute(k1_tmp,   cudaFuncAttributeMaxDynamicSharedMemorySize, smem1);
    cudaFuncSetAttribute(k2_fused, cudaFuncAttributeMaxDynamicSharedMemorySize, smem2);

    dim3 g1(128, (NBI + 127) / 128);   // 128 x 7
    k1_tmp<<<g1, 256, smem1>>>(x, W_bil);
    k2_fused<<<NBI, 256, smem2>>>(x, b_bil, ln_g, ln_b, W1, b1, w2, b2);

    int tot = BB * LL * LL;
    k3_sym<<<(tot + 255) / 256, 256>>>(out);
}